// round 2
// baseline (speedup 1.0000x reference)
// R2: resubmission of R1 kernel (R1 failed on broker infra, no kernel signal).
#include <cuda_runtime.h>
#include <math.h>
#include <float.h>
#include <stdint.h>

// ---------------- problem constants ----------------
#define BATCH 2
#define SEQ   8192
#define DIM   1024
#define HEADS 8
#define DHEAD 64
#define HDIM  512      // HEADS*DIM_HEAD
#define QKVD  1536     // 3*HDIM
#define WIN   64
#define NWIN  128      // SEQ/WIN
#define NSEL  1024
#define KVLEN 1025     // NSEL + null

// ---------------- scratch (device globals; no allocation allowed) ----------------
__device__ float g_xn[(size_t)BATCH*SEQ*DIM];        // layernormed x
__device__ float g_qkv[(size_t)BATCH*SEQ*QKVD];      // light qkv
__device__ float g_lattn[(size_t)BATCH*SEQ*HDIM];    // light attn pre-proj
__device__ float g_sq[BATCH*SEQ];
__device__ float g_skv[BATCH*SEQ];
__device__ int   g_idx[2*BATCH*NSEL];                // [which][b][j]
__device__ float g_rt[(size_t)2*BATCH*NSEL*DIM];     // rmsnormed routed (q then kv)
__device__ float g_qh[(size_t)BATCH*NSEL*HDIM];      // heavy q
__device__ float g_kvt[(size_t)DIM*DIM];             // transposed kv weight
__device__ float g_kv[(size_t)BATCH*NSEL*DIM];       // heavy kv (k|v per head)
__device__ float g_k[(size_t)BATCH*HEADS*KVLEN*DHEAD];
__device__ float g_v[(size_t)BATCH*HEADS*KVLEN*DHEAD];
__device__ float g_hattn[(size_t)BATCH*NSEL*HDIM];
__device__ float g_ho[(size_t)BATCH*NSEL*DIM];

// ---------------- layernorm ----------------
__global__ void ln_kernel(const float* __restrict__ x, const float* __restrict__ g,
                          const float* __restrict__ bta) {
    int row = blockIdx.x;                 // 0..BATCH*SEQ-1
    const float* xr = x + (size_t)row * DIM;
    int t = threadIdx.x;
    float v[4]; float s = 0.f;
#pragma unroll
    for (int i = 0; i < 4; i++) { v[i] = xr[t + 256*i]; s += v[i]; }
    __shared__ float red[256];
    red[t] = s; __syncthreads();
    for (int k = 128; k > 0; k >>= 1) { if (t < k) red[t] += red[t+k]; __syncthreads(); }
    float mu = red[0] * (1.0f/DIM); __syncthreads();
    float s2 = 0.f;
#pragma unroll
    for (int i = 0; i < 4; i++) { float d = v[i]-mu; s2 += d*d; }
    red[t] = s2; __syncthreads();
    for (int k = 128; k > 0; k >>= 1) { if (t < k) red[t] += red[t+k]; __syncthreads(); }
    float inv = 1.0f / sqrtf(red[0] * (1.0f/DIM) + 1e-5f);
#pragma unroll
    for (int i = 0; i < 4; i++) {
        int d = t + 256*i;
        g_xn[(size_t)row*DIM + d] = (v[i]-mu)*inv*g[d] + bta[d];
    }
}

// ---------------- SGEMM: C[M,N] = A[M,K]@B[K,N] (+ bias[col]) ----------------
// All dims multiples of 128 (M,N) / 8 (K).
__global__ __launch_bounds__(256) void sgemm_kernel(
        const float* __restrict__ A, const float* __restrict__ B,
        float* __restrict__ C, int M, int N, int K, const float* __restrict__ bias) {
    __shared__ float As[8][128];
    __shared__ float Bs[8][128];
    int t = threadIdx.x;
    int bm = blockIdx.y * 128, bn = blockIdx.x * 128;
    int arow = t >> 1, acol = (t & 1) * 4;
    int brow = t >> 5, bcol = (t & 31) * 4;
    const float* Ap = A + (size_t)(bm + arow) * K + acol;
    const float* Bp = B + (size_t)brow * N + bn + bcol;
    float acc[8][8];
#pragma unroll
    for (int i = 0; i < 8; i++)
#pragma unroll
        for (int j = 0; j < 8; j++) acc[i][j] = 0.f;
    int tr = (t >> 4) * 8, tc = (t & 15) * 8;
    for (int k0 = 0; k0 < K; k0 += 8) {
        float4 a4 = *(const float4*)(Ap + k0);
        float4 b4 = *(const float4*)(Bp + (size_t)k0 * N);
        As[acol+0][arow] = a4.x; As[acol+1][arow] = a4.y;
        As[acol+2][arow] = a4.z; As[acol+3][arow] = a4.w;
        *(float4*)&Bs[brow][bcol] = b4;
        __syncthreads();
#pragma unroll
        for (int k = 0; k < 8; k++) {
            float ar[8], br[8];
#pragma unroll
            for (int i = 0; i < 8; i++) ar[i] = As[k][tr+i];
#pragma unroll
            for (int j = 0; j < 8; j++) br[j] = Bs[k][tc+j];
#pragma unroll
            for (int i = 0; i < 8; i++)
#pragma unroll
                for (int j = 0; j < 8; j++) acc[i][j] = fmaf(ar[i], br[j], acc[i][j]);
        }
        __syncthreads();
    }
#pragma unroll
    for (int i = 0; i < 8; i++) {
        float* Cp = C + (size_t)(bm + tr + i) * N + bn + tc;
#pragma unroll
        for (int j = 0; j < 8; j++) {
            float v = acc[i][j];
            if (bias) v += bias[bn + tc + j];
            Cp[j] = v;
        }
    }
}

// ---------------- light (windowed) attention ----------------
// grid (NWIN, HEADS, BATCH), block 256, dyn smem
__global__ __launch_bounds__(256) void light_attn_kernel() {
    extern __shared__ float lsm[];
    float* sq = lsm;               // 64 x 65
    float* sk = sq + 64*65;        // 192 x 65 (k, then reused for v)
    float* sp = sk + 192*65;       // 64 x 193
    int win = blockIdx.x, h = blockIdx.y, b = blockIdx.z;
    int t = threadIdx.x;
    for (int e = t; e < 64*64; e += 256) {
        int i = e >> 6, d = e & 63;
        int n = win*64 + i;
        sq[i*65 + d] = g_qkv[((size_t)(b*SEQ + n))*QKVD + h*64 + d] * 0.125f;
    }
    int nbase = (win - 1) * 64;
    for (int e = t; e < 192*64; e += 256) {
        int j = e >> 6, d = e & 63;
        int n = nbase + j;
        sk[j*65 + d] = (n >= 0 && n < SEQ)
            ? g_qkv[((size_t)(b*SEQ + n))*QKVD + 512 + h*64 + d] : 0.f;
    }
    __syncthreads();
    int qi = t >> 2, g = t & 3;
    int iabs = win*64 + qi;
    float lmax = -FLT_MAX;
    const float* qrow = &sq[qi*65];
    for (int jj = 0; jj < 48; jj += 4) {
        int j = g*48 + jj;
        const float* k0 = &sk[(j+0)*65];
        const float* k1 = &sk[(j+1)*65];
        const float* k2 = &sk[(j+2)*65];
        const float* k3 = &sk[(j+3)*65];
        float s0=0.f, s1=0.f, s2=0.f, s3=0.f;
#pragma unroll 16
        for (int d = 0; d < 64; d++) {
            float qv = qrow[d];
            s0 = fmaf(qv, k0[d], s0); s1 = fmaf(qv, k1[d], s1);
            s2 = fmaf(qv, k2[d], s2); s3 = fmaf(qv, k3[d], s3);
        }
        float sv[4] = {s0, s1, s2, s3};
#pragma unroll
        for (int u = 0; u < 4; u++) {
            int jabs = nbase + j + u;
            bool valid = (jabs >= 0) && (jabs < SEQ) && (abs(iabs - jabs) <= WIN);
            float val = valid ? sv[u] : -FLT_MAX;
            sp[qi*193 + j + u] = val;
            lmax = fmaxf(lmax, val);
        }
    }
    lmax = fmaxf(lmax, __shfl_xor_sync(0xFFFFFFFFu, lmax, 1));
    lmax = fmaxf(lmax, __shfl_xor_sync(0xFFFFFFFFu, lmax, 2));
    float lsum = 0.f;
    for (int jj = 0; jj < 48; jj++) {
        int j = g*48 + jj;
        float p = expf(sp[qi*193 + j] - lmax);
        sp[qi*193 + j] = p;
        lsum += p;
    }
    lsum += __shfl_xor_sync(0xFFFFFFFFu, lsum, 1);
    lsum += __shfl_xor_sync(0xFFFFFFFFu, lsum, 2);
    __syncthreads();
    // load v over k
    for (int e = t; e < 192*64; e += 256) {
        int j = e >> 6, d = e & 63;
        int n = nbase + j;
        sk[j*65 + d] = (n >= 0 && n < SEQ)
            ? g_qkv[((size_t)(b*SEQ + n))*QKVD + 1024 + h*64 + d] : 0.f;
    }
    __syncthreads();
    float invl = 1.0f / lsum;
    float acc[16];
#pragma unroll
    for (int r = 0; r < 16; r++) acc[r] = 0.f;
    for (int j = 0; j < 192; j++) {
        float p = sp[qi*193 + j];
        const float* vrow = &sk[j*65 + g*16];
#pragma unroll
        for (int r = 0; r < 16; r++) acc[r] = fmaf(p, vrow[r], acc[r]);
    }
#pragma unroll
    for (int r = 0; r < 16; r++)
        g_lattn[((size_t)(b*SEQ + iabs))*HDIM + h*64 + g*16 + r] = acc[r] * invl;
}

// ---------------- routing scores ----------------
__global__ void route_score_kernel(const float* __restrict__ x,
                                   const float* __restrict__ qt,
                                   const float* __restrict__ kt) {
    int row = blockIdx.x;
    int t = threadIdx.x;
    const float* xr = x + (size_t)row * DIM;
    float sq = 0.f, sk = 0.f;
#pragma unroll
    for (int i = t; i < DIM; i += 256) {
        float v = xr[i];
        sq = fmaf(v, qt[i], sq);
        sk = fmaf(v, kt[i], sk);
    }
    __shared__ float r1[256], r2[256];
    r1[t] = sq; r2[t] = sk; __syncthreads();
    for (int k = 128; k > 0; k >>= 1) {
        if (t < k) { r1[t] += r1[t+k]; r2[t] += r2[t+k]; }
        __syncthreads();
    }
    if (t == 0) { g_sq[row] = r1[0]; g_skv[row] = r2[0]; }
}

// ---------------- coordinate descent + exact top-k (bitonic) ----------------
// grid (BATCH, 2), block 1024, dyn smem = 8192*8 + 2*8192*4 = 131072 bytes
__global__ __launch_bounds__(1024) void route_select_kernel() {
    extern __shared__ unsigned char rsm[];
    unsigned long long* key = (unsigned long long*)rsm;   // 8192
    float* s  = (float*)(key + SEQ);
    float* bb = s + SEQ;
    __shared__ float red[1024];
    int b = blockIdx.x, which = blockIdx.y;
    int t = threadIdx.x;
    const float* src = which ? g_skv : g_sq;
    for (int i = t; i < SEQ; i += 1024) { float v = src[b*SEQ + i]; s[i] = v; bb[i] = -v; }
    __syncthreads();
    float cur = 4.0f;
    const float logk = logf(1152.0f);   // eff_k = NSEL * 9/8
    float a = 0.f;
    for (int it = 0; it < 20; it++) {
        float m = -FLT_MAX;
        for (int i = t; i < SEQ; i += 1024) m = fmaxf(m, (s[i] + bb[i]) / cur);
        red[t] = m; __syncthreads();
        for (int k = 512; k > 0; k >>= 1) { if (t < k) red[t] = fmaxf(red[t], red[t+k]); __syncthreads(); }
        m = red[0]; __syncthreads();
        float sum = 0.f;
        for (int i = t; i < SEQ; i += 1024) sum += expf((s[i] + bb[i]) / cur - m);
        red[t] = sum; __syncthreads();
        for (int k = 512; k > 0; k >>= 1) { if (t < k) red[t] += red[t+k]; __syncthreads(); }
        float lse = m + logf(red[0]);
        a = cur * (logk - lse);
        __syncthreads();
        for (int i = t; i < SEQ; i += 1024) bb[i] = -fmaxf(s[i] + a, 0.f);
        cur = fmaxf(cur * 0.7f, 0.03f);
        __syncthreads();
    }
    // scores & pack keys: (score desc, idx asc) via uint64 descending sort
    for (int i = t; i < SEQ; i += 1024) {
        float ta = s[i] + a;
        float sc = expf((ta + bb[i]) / cur);   // ta + (-relu(ta)) == 0 exactly when ta>0
        unsigned int sb = __float_as_uint(sc); // sc >= 0 -> order-preserving
        key[i] = ((unsigned long long)sb << 32)
               | (unsigned long long)(0xFFFFFFFFu - (unsigned)i);
    }
    __syncthreads();
    for (int size = 2; size <= SEQ; size <<= 1) {
        for (int stride = size >> 1; stride > 0; stride >>= 1) {
            for (int i = t; i < SEQ; i += 1024) {
                int j = i ^ stride;
                if (j > i) {
                    bool desc = ((i & size) == 0);
                    unsigned long long ki = key[i], kj = key[j];
                    if ((ki < kj) == desc) { key[i] = kj; key[j] = ki; }
                }
            }
            __syncthreads();
        }
    }
    if (t < NSEL) {
        unsigned idxv = 0xFFFFFFFFu - (unsigned)(key[t] & 0xFFFFFFFFull);
        g_idx[(which*BATCH + b)*NSEL + t] = (int)idxv;
    }
}

// ---------------- gather routed tokens + rmsnorm ----------------
// grid (NSEL, BATCH, 2)
__global__ void gather_rms_kernel(const float* __restrict__ x,
                                  const float* __restrict__ gamma) {
    int j = blockIdx.x, b = blockIdx.y, which = blockIdx.z;
    int idx = g_idx[(which*BATCH + b)*NSEL + j];
    const float* xr = x + ((size_t)b*SEQ + idx)*DIM;
    int t = threadIdx.x;
    float v[4]; float ss = 0.f;
#pragma unroll
    for (int i = 0; i < 4; i++) { v[i] = xr[t + 256*i]; ss += v[i]*v[i]; }
    __shared__ float red[256];
    red[t] = ss; __syncthreads();
    for (int k = 128; k > 0; k >>= 1) { if (t < k) red[t] += red[t+k]; __syncthreads(); }
    float nrm = sqrtf(red[0]);
    float scale = 32.0f / fmaxf(nrm, 1e-12f);   // sqrt(1024)=32
    float* dst = g_rt + (((size_t)which*BATCH + b)*NSEL + j)*DIM;
#pragma unroll
    for (int i = 0; i < 4; i++) { int d = t + 256*i; dst[d] = v[i]*scale*gamma[d]; }
}

// ---------------- rope on heavy q (in-place) ----------------
__global__ void rope_q_kernel() {
    int e = blockIdx.x*256 + threadIdx.x;  // BATCH*NSEL*HEADS*32
    int d = e & 31;
    int h = (e >> 5) & 7;
    int j = (e >> 8) & 1023;
    int b = e >> 18;
    int tpos = g_idx[b*NSEL + j];
    float invf = powf(10000.0f, -(float)d / 32.0f);
    float th = (float)tpos * invf;            // fp32 rounding matches reference
    double cd, sd; sincos((double)th, &sd, &cd);
    float c = (float)cd, sn = (float)sd;
    size_t base = ((size_t)(b*NSEL + j))*HDIM + h*DHEAD;
    float x1 = g_qh[base + d], x2 = g_qh[base + d + 32];
    g_qh[base + d]      = x1*c - x2*sn;
    g_qh[base + d + 32] = x2*c + x1*sn;
}

// ---------------- transpose heavy kv weight: [1024][1024] -> B[i][h*128+dd] ----------------
__global__ void transpose_kvw_kernel(const float* __restrict__ w) {
    __shared__ float tile[32][33];
    int bx = blockIdx.x * 32, by = blockIdx.y * 32; // bx: i, by: r=(h*128+dd)
    int tx = threadIdx.x, ty = threadIdx.y;
    for (int k = 0; k < 32; k += 8)
        tile[ty + k][tx] = w[(size_t)(by + ty + k)*DIM + bx + tx];
    __syncthreads();
    for (int k = 0; k < 32; k += 8)
        g_kvt[(size_t)(bx + ty + k)*DIM + by + tx] = tile[tx][ty + k];
}

// ---------------- pack k/v with rope + null kv ----------------
__global__ void pack_kv_kernel(const float* __restrict__ null_kv) {
    int e = blockIdx.x*256 + threadIdx.x;  // BATCH*HEADS*KVLEN*32
    if (e >= BATCH*HEADS*KVLEN*32) return;
    int d  = e & 31;
    int jj = (e >> 5) % KVLEN;
    int hb = (e >> 5) / KVLEN;
    int h = hb & 7, b = hb >> 3;
    size_t obase = ((size_t)(b*HEADS + h)*KVLEN + jj)*DHEAD;
    if (jj == 0) {
        g_k[obase + d]      = null_kv[h*DHEAD + d];
        g_k[obase + d + 32] = null_kv[h*DHEAD + d + 32];
        g_v[obase + d]      = null_kv[HEADS*DHEAD + h*DHEAD + d];
        g_v[obase + d + 32] = null_kv[HEADS*DHEAD + h*DHEAD + d + 32];
    } else {
        int j = jj - 1;
        int tpos = g_idx[(BATCH + b)*NSEL + j];   // kv indices
        size_t ibase = ((size_t)(b*NSEL + j))*DIM + h*128;
        float k1 = g_kv[ibase + d], k2 = g_kv[ibase + d + 32];
        float invf = powf(10000.0f, -(float)d / 32.0f);
        float th = (float)tpos * invf;
        double cd, sd; sincos((double)th, &sd, &cd);
        float c = (float)cd, sn = (float)sd;
        g_k[obase + d]      = k1*c - k2*sn;
        g_k[obase + d + 32] = k2*c + k1*sn;
        g_v[obase + d]      = g_kv[ibase + 64 + d];       // score_kv == 1.0 exactly
        g_v[obase + d + 32] = g_kv[ibase + 64 + d + 32];
    }
}

// ---------------- heavy attention (online softmax over 1025 keys) ----------------
// grid (16, HEADS, BATCH), block 256, dyn smem
__global__ __launch_bounds__(256) void heavy_attn_kernel() {
    extern __shared__ float hsm[];
    float* sq = hsm;               // 64 x 65
    float* sk = sq + 64*65;        // 128 x 65
    float* sv = sk + 128*65;       // 128 x 65
    float* sp = sv + 128*65;       // 64 x 129
    int qt = blockIdx.x, h = blockIdx.y, b = blockIdx.z;
    int t = threadIdx.x;
    for (int e = t; e < 64*64; e += 256) {
        int i = e >> 6, d = e & 63;
        sq[i*65 + d] = g_qh[((size_t)(b*NSEL + qt*64 + i))*HDIM + h*64 + d] * 0.125f;
    }
    int qi = t >> 2, g = t & 3;
    float m = -FLT_MAX, l = 0.f;
    float acc[16];
#pragma unroll
    for (int r = 0; r < 16; r++) acc[r] = 0.f;
    size_t kvbase = ((size_t)(b*HEADS + h))*KVLEN*DHEAD;
    for (int c0 = 0; c0 < KVLEN; c0 += 128) {
        int cnt = min(128, KVLEN - c0);
        __syncthreads();   // protect smem reuse vs previous chunk
        for (int e = t; e < 128*64; e += 256) {
            int j = e >> 6, d = e & 63;
            bool ok = j < cnt;
            sk[j*65 + d] = ok ? g_k[kvbase + (size_t)(c0 + j)*DHEAD + d] : 0.f;
            sv[j*65 + d] = ok ? g_v[kvbase + (size_t)(c0 + j)*DHEAD + d] : 0.f;
        }
        __syncthreads();
        float svals[32];
        float cm = -FLT_MAX;
        const float* qrow = &sq[qi*65];
        for (int jj = 0; jj < 32; jj += 4) {
            int j = g*32 + jj;
            const float* k0 = &sk[(j+0)*65];
            const float* k1 = &sk[(j+1)*65];
            const float* k2 = &sk[(j+2)*65];
            const float* k3 = &sk[(j+3)*65];
            float s0=0.f, s1=0.f, s2=0.f, s3=0.f;
#pragma unroll 16
            for (int d = 0; d < 64; d++) {
                float qv = qrow[d];
                s0 = fmaf(qv, k0[d], s0); s1 = fmaf(qv, k1[d], s1);
                s2 = fmaf(qv, k2[d], s2); s3 = fmaf(qv, k3[d], s3);
            }
            float sv4[4] = {s0, s1, s2, s3};
#pragma unroll
            for (int u = 0; u < 4; u++) {
                float sx = (j + u < cnt) ? sv4[u] : -FLT_MAX;
                svals[jj + u] = sx;
                cm = fmaxf(cm, sx);
            }
        }
        cm = fmaxf(cm, __shfl_xor_sync(0xFFFFFFFFu, cm, 1));
        cm = fmaxf(cm, __shfl_xor_sync(0xFFFFFFFFu, cm, 2));
        float mn = fmaxf(m, cm);
        float scale = expf(m - mn);
        float ls = 0.f;
        for (int jj = 0; jj < 32; jj++) {
            float p = expf(svals[jj] - mn);
            sp[qi*129 + g*32 + jj] = p;
            ls += p;
        }
        ls += __shfl_xor_sync(0xFFFFFFFFu, ls, 1);
        ls += __shfl_xor_sync(0xFFFFFFFFu, ls, 2);
        l = l*scale + ls;
        m = mn;
#pragma unroll
        for (int r = 0; r < 16; r++) acc[r] *= scale;
        __syncwarp();
        for (int jj = 0; jj < 128; jj++) {
            float p = sp[qi*129 + jj];
            const float* vrow = &sv[jj*65 + g*16];
#pragma unroll
            for (int r = 0; r < 16; r++) acc[r] = fmaf(p, vrow[r], acc[r]);
        }
    }
    float invl = 1.0f / l;
#pragma unroll
    for (int r = 0; r < 16; r++)
        g_hattn[((size_t)(b*NSEL + qt*64 + qi))*HDIM + h*64 + g*16 + r] = acc[r] * invl;
}

// ---------------- scatter heavy rows into output ----------------
__global__ void scatter_kernel(float* __restrict__ out, const float* __restrict__ nullq) {
    int j = blockIdx.x & 1023, b = blockIdx.x >> 10;
    int i = g_idx[b*NSEL + j];
    float* orow = out + ((size_t)b*SEQ + i)*DIM;
    const float* hrow = g_ho + ((size_t)(b*NSEL + j))*DIM;
    for (int d = threadIdx.x; d < DIM; d += 256)
        orow[d] += hrow[d] - nullq[d];
}

// ---------------- launch ----------------
extern "C" void kernel_launch(void* const* d_in, const int* in_sizes, int n_in,
                              void* d_out, int out_size) {
    const float* x       = (const float*)d_in[0];
    const float* ln_g    = (const float*)d_in[1];
    const float* ln_b    = (const float*)d_in[2];
    const float* qkv_w   = (const float*)d_in[3];
    const float* lout_w  = (const float*)d_in[4];
    const float* q_tok   = (const float*)d_in[5];
    const float* kv_tok  = (const float*)d_in[6];
    const float* hgamma  = (const float*)d_in[7];
    const float* hq_w    = (const float*)d_in[8];
    const float* hkv_w   = (const float*)d_in[9];
    const float* hnullkv = (const float*)d_in[10];
    const float* hout_w  = (const float*)d_in[11];
    const float* nullq   = (const float*)d_in[12];
    float* out = (float*)d_out;

    float *p_xn, *p_qkv, *p_lattn, *p_rt, *p_qh, *p_kvt, *p_kv, *p_hattn, *p_ho;
    cudaGetSymbolAddress((void**)&p_xn, g_xn);
    cudaGetSymbolAddress((void**)&p_qkv, g_qkv);
    cudaGetSymbolAddress((void**)&p_lattn, g_lattn);
    cudaGetSymbolAddress((void**)&p_rt, g_rt);
    cudaGetSymbolAddress((void**)&p_qh, g_qh);
    cudaGetSymbolAddress((void**)&p_kvt, g_kvt);
    cudaGetSymbolAddress((void**)&p_kv, g_kv);
    cudaGetSymbolAddress((void**)&p_hattn, g_hattn);
    cudaGetSymbolAddress((void**)&p_ho, g_ho);

    const int LSMEM = (64*65 + 192*65 + 64*193) * 4;                 // 115968
    const int HSMEM = (64*65 + 128*65 + 128*65 + 64*129) * 4;        // 116224
    const int RSMEM = SEQ*8 + 2*SEQ*4;                               // 131072
    cudaFuncSetAttribute(light_attn_kernel,  cudaFuncAttributeMaxDynamicSharedMemorySize, LSMEM);
    cudaFuncSetAttribute(heavy_attn_kernel,  cudaFuncAttributeMaxDynamicSharedMemorySize, HSMEM);
    cudaFuncSetAttribute(route_select_kernel, cudaFuncAttributeMaxDynamicSharedMemorySize, RSMEM);

    // ---- light path ----
    ln_kernel<<<BATCH*SEQ, 256>>>(x, ln_g, ln_b);
    sgemm_kernel<<<dim3(QKVD/128, (BATCH*SEQ)/128), 256>>>(p_xn, qkv_w, p_qkv,
        BATCH*SEQ, QKVD, DIM, nullptr);
    light_attn_kernel<<<dim3(NWIN, HEADS, BATCH), 256, LSMEM>>>();
    sgemm_kernel<<<dim3(DIM/128, (BATCH*SEQ)/128), 256>>>(p_lattn, lout_w, out,
        BATCH*SEQ, DIM, HDIM, nullq);   // out = light_out + null (everywhere)

    // ---- routing ----
    route_score_kernel<<<BATCH*SEQ, 256>>>(x, q_tok, kv_tok);
    route_select_kernel<<<dim3(BATCH, 2), 1024, RSMEM>>>();

    // ---- heavy path ----
    gather_rms_kernel<<<dim3(NSEL, BATCH, 2), 256>>>(x, hgamma);
    sgemm_kernel<<<dim3(HDIM/128, (BATCH*NSEL)/128), 256>>>(p_rt, hq_w, p_qh,
        BATCH*NSEL, HDIM, DIM, nullptr);
    rope_q_kernel<<<(BATCH*NSEL*HEADS*32)/256, 256>>>();
    transpose_kvw_kernel<<<dim3(32, 32), dim3(32, 8)>>>(hkv_w);
    sgemm_kernel<<<dim3(DIM/128, (BATCH*NSEL)/128), 256>>>(p_rt + (size_t)BATCH*NSEL*DIM,
        p_kvt, p_kv, BATCH*NSEL, DIM, DIM, nullptr);
    pack_kv_kernel<<<(BATCH*HEADS*KVLEN*32 + 255)/256, 256>>>(hnullkv);
    heavy_attn_kernel<<<dim3(16, HEADS, BATCH), 256, HSMEM>>>();
    sgemm_kernel<<<dim3(DIM/128, (BATCH*NSEL)/128), 256>>>(p_hattn, hout_w, p_ho,
        BATCH*NSEL, DIM, HDIM, nullptr);
    scatter_kernel<<<BATCH*NSEL, 256>>>(out, nullq);
}